// round 16
// baseline (speedup 1.0000x reference)
#include <cuda_runtime.h>
#include <cuda_bf16.h>
#include <cuda_fp16.h>
#include <cstdint>

// ---------------------------------------------------------------------------
// CausalSelfAttention on GB300 (sm_103 family target — no 'a' features).
// fp16 1-pass mma.sync everywhere; co-resident CTAs for latency hiding:
//   gemm1/gemm3: unified 128x128 kernel, __launch_bounds__(256,2) -> 2 CTA/SM
//   attention:   64 q-rows/CTA, 128 thr, 2 CTA/SM; S,PV 1-pass fp16
// ---------------------------------------------------------------------------

#define B_ 4
#define T_ 2048
#define C_ 768
#define H_ 12
#define ROWS_ 8192
#define QKVC_ 2304

// ---------------- scratch ---------------------------------------------------
__device__ __align__(256) __half  g_qkv[ROWS_ * QKVC_];     // Q(scaled),K,V fp16
__device__ __align__(256) __half  g_x[ROWS_ * C_];          // x fp16
__device__ __align__(256) __half  g_y[ROWS_ * C_];          // y fp16
__device__ __align__(256) __half  g_wa[QKVC_ * C_];         // w_attn^T fp16
__device__ __align__(256) __half  g_wp[C_ * C_];            // w_proj^T fp16

// ---------------- helpers ---------------------------------------------------
__device__ __forceinline__ uint32_t smem_u32(const void* p) {
    uint32_t a;
    asm("{ .reg .u64 t; cvta.to.shared.u64 t, %1; cvt.u32.u64 %0, t; }"
        : "=r"(a) : "l"(p));
    return a;
}
#define SWZ(x) ((x) ^ (((x) >> 3) & 0x70))

__device__ __forceinline__ void cpa16(uint32_t dst, const void* src) {
    asm volatile("cp.async.cg.shared.global [%0], [%1], 16;" :: "r"(dst), "l"(src));
}
__device__ __forceinline__ void cpa_commit() { asm volatile("cp.async.commit_group;"); }

__device__ __forceinline__ void ldsm_x4(uint32_t& r0, uint32_t& r1, uint32_t& r2,
                                        uint32_t& r3, uint32_t addr) {
    asm volatile("ldmatrix.sync.aligned.m8n8.x4.shared.b16 {%0,%1,%2,%3}, [%4];"
                 : "=r"(r0), "=r"(r1), "=r"(r2), "=r"(r3) : "r"(addr));
}
__device__ __forceinline__ void ldsm_x4t(uint32_t& r0, uint32_t& r1, uint32_t& r2,
                                         uint32_t& r3, uint32_t addr) {
    asm volatile("ldmatrix.sync.aligned.m8n8.x4.trans.shared.b16 {%0,%1,%2,%3}, [%4];"
                 : "=r"(r0), "=r"(r1), "=r"(r2), "=r"(r3) : "r"(addr));
}
__device__ __forceinline__ void mma_f16(float* c, const uint32_t* a,
                                        uint32_t b0, uint32_t b1) {
    asm volatile("mma.sync.aligned.m16n8k16.row.col.f32.f16.f16.f32 "
                 "{%0,%1,%2,%3}, {%4,%5,%6,%7}, {%8,%9}, {%0,%1,%2,%3};"
                 : "+f"(c[0]), "+f"(c[1]), "+f"(c[2]), "+f"(c[3])
                 : "r"(a[0]), "r"(a[1]), "r"(a[2]), "r"(a[3]), "r"(b0), "r"(b1));
}
__device__ __forceinline__ float ex2_(float x) {
    float r; asm("ex2.approx.f32 %0, %1;" : "=f"(r) : "f"(x)); return r;
}
__device__ __forceinline__ uint32_t packh2(float a, float b) {
    __half2 hh = __floats2half2_rn(a, b);
    return *(uint32_t*)&hh;
}

// ---------------------------------------------------------------------------
// Conversion kernels
// ---------------------------------------------------------------------------
__global__ void convert_rows_h_kernel(const float* __restrict__ in,
                                      __half* __restrict__ outh, int n4)
{
    int i = blockIdx.x * blockDim.x + threadIdx.x;
    if (i >= n4) return;
    float4 v = ((const float4*)in)[i];
    uint32_t* hp = (uint32_t*)(outh + 4 * (size_t)i);
    hp[0] = packh2(v.x, v.y);
    hp[1] = packh2(v.z, v.w);
}

__global__ void transpose_h_kernel(const float* __restrict__ w,
                                   __half* __restrict__ wT, int K, int N)
{
    __shared__ float t[32][33];
    const int n0 = blockIdx.x * 32, k0 = blockIdx.y * 32;
    const int tx = threadIdx.x, ty = threadIdx.y;
#pragma unroll
    for (int j = 0; j < 4; j++)
        t[ty + j * 8][tx] = w[(size_t)(k0 + ty + j * 8) * N + n0 + tx];
    __syncthreads();
#pragma unroll
    for (int j = 0; j < 4; j++) {
        const int n = ty + j * 8;
        wT[(size_t)(n0 + n) * K + k0 + tx] = __float2half(t[tx][n]);
    }
}

// ---------------------------------------------------------------------------
// Unified fp16 1-pass GEMM: C = A[M,K] @ B[N,K]^T + bias
// 128x128 CTA tile, 8 warps 64x32, 3-stage single-sync pipeline, 2 CTAs/SM.
// EPI 0: fp32 out.  EPI 1: fp16 out, cols<768 scaled by log2e/8 (qkv).
// ---------------------------------------------------------------------------
#define G_STAGE 32768          // A 16K | B 16K
#define G_SMEM  (3 * G_STAGE)

__device__ __forceinline__ void gemm_load_chunk(
    uint32_t sb, const __half* Am, const __half* Bm,
    int rowBase, int colBase, int K, int kc, int stage, int tid)
{
    const uint32_t base = sb + stage * G_STAGE;
    const int k0 = kc * 64;
#pragma unroll
    for (int i = 0; i < 4; i++) {
        const int seg = tid + i * 256;
        const int r = seg >> 3, g = seg & 7;
        const uint32_t soff = SWZ(r * 128 + g * 16);
        cpa16(base + soff,         Am + (size_t)(rowBase + r) * K + k0 + g * 8);
        cpa16(base + 16384 + soff, Bm + (size_t)(colBase + r) * K + k0 + g * 8);
    }
    cpa_commit();
}

template <int EPI>
__global__ __launch_bounds__(256, 2)
void gemm_f16_kernel(const __half* __restrict__ Am, const __half* __restrict__ Bm,
                     const float* __restrict__ bias, float* __restrict__ Cf,
                     __half* __restrict__ Ch, int M, int N, int K)
{
    extern __shared__ char smem[];
    const uint32_t sb = smem_u32(smem);
    const int tid = threadIdx.x, wid = tid >> 5, lane = tid & 31;
    const int wm = wid >> 2, wn = wid & 3;
    const int rowBase = blockIdx.y * 128, colBase = blockIdx.x * 128;
    const int NK = K / 64;

    float c[4][4][4];
#pragma unroll
    for (int i = 0; i < 4; i++)
#pragma unroll
        for (int j = 0; j < 4; j++)
#pragma unroll
            for (int k = 0; k < 4; k++) c[i][j][k] = 0.f;

    gemm_load_chunk(sb, Am, Bm, rowBase, colBase, K, 0, 0, tid);
    gemm_load_chunk(sb, Am, Bm, rowBase, colBase, K, 1, 1, tid);

    const int aRow = wm * 64 + (lane & 15);
    const uint32_t aSegOff = ((lane >> 4) & 1) * 16;
    const int bRow4 = wn * 32 + ((lane >> 4) & 1) * 8 + (lane & 7);
    const uint32_t bSegOff = ((lane >> 3) & 1) * 16;

    for (int kc = 0; kc < NK; kc++) {
        if (kc + 1 < NK) asm volatile("cp.async.wait_group 1;" ::: "memory");
        else             asm volatile("cp.async.wait_group 0;" ::: "memory");
        __syncthreads();
        if (kc + 2 < NK)
            gemm_load_chunk(sb, Am, Bm, rowBase, colBase, K,
                            kc + 2, (kc + 2) % 3, tid);
        const uint32_t st = sb + (kc % 3) * G_STAGE;
#pragma unroll
        for (int ks = 0; ks < 4; ks++) {
            uint32_t bf[4][2];
#pragma unroll
            for (int nj = 0; nj < 4; nj += 2) {
                const uint32_t boff = SWZ((uint32_t)(bRow4 + nj * 8) * 128 + ks * 32 + bSegOff);
                ldsm_x4(bf[nj][0], bf[nj][1], bf[nj + 1][0], bf[nj + 1][1], st + 16384 + boff);
            }
#pragma unroll
            for (int mi = 0; mi < 4; mi++) {
                uint32_t af[4];
                const uint32_t aoff = SWZ((uint32_t)(aRow + mi * 16) * 128 + ks * 32 + aSegOff);
                ldsm_x4(af[0], af[1], af[2], af[3], st + aoff);
#pragma unroll
                for (int nj = 0; nj < 4; nj++)
                    mma_f16(c[mi][nj], af, bf[nj][0], bf[nj][1]);
            }
        }
    }

    const int g = lane >> 2, q2 = (lane & 3) * 2;
    if (EPI == 0) {
#pragma unroll
        for (int mi = 0; mi < 4; mi++) {
            const int row0 = rowBase + wm * 64 + mi * 16 + g;
#pragma unroll
            for (int nj = 0; nj < 4; nj++) {
                const int col = colBase + wn * 32 + nj * 8 + q2;
                const float bx = bias[col], by = bias[col + 1];
                float2 v0 = make_float2(c[mi][nj][0] + bx, c[mi][nj][1] + by);
                float2 v1 = make_float2(c[mi][nj][2] + bx, c[mi][nj][3] + by);
                *(float2*)(Cf + (size_t)row0 * N + col) = v0;
                *(float2*)(Cf + (size_t)(row0 + 8) * N + col) = v1;
            }
        }
    } else {
        const float scl = (colBase < 768) ? 0.18033688f : 1.0f;
#pragma unroll
        for (int mi = 0; mi < 4; mi++) {
            const int row0 = rowBase + wm * 64 + mi * 16 + g;
#pragma unroll
            for (int nj = 0; nj < 4; nj++) {
                const int col = colBase + wn * 32 + nj * 8 + q2;
                const float bx = bias[col], by = bias[col + 1];
                *(uint32_t*)(Ch + (size_t)row0 * N + col) =
                    packh2((c[mi][nj][0] + bx) * scl, (c[mi][nj][1] + by) * scl);
                *(uint32_t*)(Ch + (size_t)(row0 + 8) * N + col) =
                    packh2((c[mi][nj][2] + bx) * scl, (c[mi][nj][3] + by) * scl);
            }
        }
    }
}

// ---------------------------------------------------------------------------
// Flash attention: 64 q-rows/CTA, 128 threads (4 warps x 16 rows), 2 CTAs/SM.
// S fp16 1-pass, PV fp16 1-pass. Single-sync 3-stage ring, stage 16K.
// S(kt+1) interleaved with softmax(kt).
// ---------------------------------------------------------------------------
#define SM_Q  0
#define SM_ST 8192
#define A_STAGE 16384
#define A_SMEM (SM_ST + 3 * A_STAGE)

__device__ __forceinline__ void attn_load_kv(
    uint32_t sb, const __half* qkv, size_t base0, int kBase, int stage, int tid)
{
    const uint32_t st = sb + SM_ST + stage * A_STAGE;
#pragma unroll
    for (int i = 0; i < 4; i++) {
        const int seg = tid + i * 128;
        const int r = seg >> 3, gsg = seg & 7;
        const size_t goff = base0 + (size_t)(kBase + r) * QKVC_ + gsg * 8;
        const uint32_t soff = SWZ((uint32_t)r * 128 + gsg * 16);
        cpa16(st + soff,        qkv + goff + 768);    // K
        cpa16(st + 8192 + soff, qkv + goff + 1536);   // V
    }
    cpa_commit();
}

__global__ __launch_bounds__(128, 2)
void attn_mma_kernel(const __half* __restrict__ qkv, __half* __restrict__ y)
{
    extern __shared__ char smem[];
    const uint32_t sb = smem_u32(smem);
    const int qt = (int)gridDim.x - 1 - (int)blockIdx.x;   // longest first
    const int bh = blockIdx.y;
    const int b = bh / H_, h = bh % H_;
    const int tid = threadIdx.x, wid = tid >> 5, lane = tid & 31;
    const int qBase = qt * 64;
    const size_t base0 = (size_t)b * T_ * QKVC_ + h * 64;
    const int ktMax = qt;

#pragma unroll
    for (int i = 0; i < 4; i++) {
        const int seg = tid + i * 128;
        const int r = seg >> 3, gsg = seg & 7;
        const size_t goff = base0 + (size_t)(qBase + r) * QKVC_ + gsg * 8;
        cpa16(sb + SM_Q + SWZ((uint32_t)r * 128 + gsg * 16), qkv + goff);
    }
    cpa_commit();
    attn_load_kv(sb, qkv, base0, 0, 0, tid);
    attn_load_kv(sb, qkv, base0, (ktMax >= 1) ? 64 : 0, 1, tid);
    asm volatile("cp.async.wait_group 1;" ::: "memory");
    __syncthreads();

    uint32_t qf[4][4];
    {
        const int aRow = wid * 16 + (lane & 15);
        const uint32_t aSeg = ((lane >> 4) & 1) * 16;
#pragma unroll
        for (int ks = 0; ks < 4; ks++) {
            const uint32_t aoff = SWZ((uint32_t)aRow * 128 + ks * 32 + aSeg);
            ldsm_x4(qf[ks][0], qf[ks][1], qf[ks][2], qf[ks][3], sb + SM_Q + aoff);
        }
    }

    float o[8][4];
#pragma unroll
    for (int d = 0; d < 8; d++)
#pragma unroll
        for (int k = 0; k < 4; k++) o[d][k] = 0.f;
    float m0 = -1e30f, m1 = -1e30f, l0s = 0.f, l1s = 0.f;

    const int g = lane >> 2, q2 = (lane & 3) * 2;
    const int qRowMin = qBase + wid * 16;
    const int row0 = qRowMin + g;

    const int bRow4 = ((lane >> 4) & 1) * 8 + (lane & 7);
    const uint32_t bSeg = ((lane >> 3) & 1) * 16;
    const int vRowL = lane & 15;
    const uint32_t vSeg = ((lane >> 4) & 1) * 16;

    float sc[8][4];
    {
        const uint32_t st0 = sb + SM_ST;
#pragma unroll
        for (int nj = 0; nj < 8; nj += 2) {
#pragma unroll
            for (int k = 0; k < 4; k++) { sc[nj][k] = 0.f; sc[nj + 1][k] = 0.f; }
#pragma unroll
            for (int ks = 0; ks < 4; ks++) {
                const uint32_t boff = SWZ((uint32_t)(nj * 8 + bRow4) * 128 + ks * 32 + bSeg);
                uint32_t k0, k1, k2, k3;
                ldsm_x4(k0, k1, k2, k3, st0 + boff);
                mma_f16(sc[nj],     qf[ks], k0, k1);
                mma_f16(sc[nj + 1], qf[ks], k2, k3);
            }
        }
    }

    for (int kt = 0; kt <= ktMax; kt++) {
        const int kBase = kt * 64;
        asm volatile("cp.async.wait_group 0;" ::: "memory");
        __syncthreads();
        if (kt + 2 <= ktMax)
            attn_load_kv(sb, qkv, base0, (kt + 2) * 64, (kt + 2) % 3, tid);

        const bool doS = (kt + 1 <= ktMax);
        const uint32_t stP = sb + SM_ST + (kt % 3) * A_STAGE;
        const uint32_t stS = sb + SM_ST + ((kt + 1) % 3) * A_STAGE;

        if (kt == ktMax) {
#pragma unroll
            for (int nj = 0; nj < 8; nj++) {
                const int col = kBase + nj * 8 + q2;
                if (col > row0)         sc[nj][0] = -1e30f;
                if (col + 1 > row0)     sc[nj][1] = -1e30f;
                if (col > row0 + 8)     sc[nj][2] = -1e30f;
                if (col + 1 > row0 + 8) sc[nj][3] = -1e30f;
            }
        }

        float mx0 = -1e30f, mx1 = -1e30f;
#pragma unroll
        for (int nj = 0; nj < 8; nj++) {
            mx0 = fmaxf(mx0, fmaxf(sc[nj][0], sc[nj][1]));
            mx1 = fmaxf(mx1, fmaxf(sc[nj][2], sc[nj][3]));
        }
        mx0 = fmaxf(mx0, __shfl_xor_sync(0xffffffffu, mx0, 1));
        mx0 = fmaxf(mx0, __shfl_xor_sync(0xffffffffu, mx0, 2));
        mx1 = fmaxf(mx1, __shfl_xor_sync(0xffffffffu, mx1, 1));
        mx1 = fmaxf(mx1, __shfl_xor_sync(0xffffffffu, mx1, 2));
        const float mn0 = fmaxf(m0, mx0), mn1 = fmaxf(m1, mx1);
        const float al0 = ex2_(m0 - mn0), al1 = ex2_(m1 - mn1);
        m0 = mn0; m1 = mn1;

        float s0 = 0.f, s1 = 0.f;
        float sn[8][4];
        if (doS) {
#pragma unroll
            for (int nj = 0; nj < 8; nj += 2) {
#pragma unroll
                for (int k = 0; k < 4; k++) { sn[nj][k] = 0.f; sn[nj + 1][k] = 0.f; }
#pragma unroll
                for (int ks = 0; ks < 4; ks++) {
                    const uint32_t boff = SWZ((uint32_t)(nj * 8 + bRow4) * 128 + ks * 32 + bSeg);
                    uint32_t k0, k1, k2, k3;
                    ldsm_x4(k0, k1, k2, k3, stS + boff);
                    mma_f16(sn[nj],     qf[ks], k0, k1);
                    mma_f16(sn[nj + 1], qf[ks], k2, k3);
                }
#pragma unroll
                for (int u = 0; u < 2; u++) {
                    sc[nj + u][0] = ex2_(sc[nj + u][0] - mn0);
                    sc[nj + u][1] = ex2_(sc[nj + u][1] - mn0);
                    sc[nj + u][2] = ex2_(sc[nj + u][2] - mn1);
                    sc[nj + u][3] = ex2_(sc[nj + u][3] - mn1);
                    s0 += sc[nj + u][0] + sc[nj + u][1];
                    s1 += sc[nj + u][2] + sc[nj + u][3];
                }
            }
        } else {
#pragma unroll
            for (int nj = 0; nj < 8; nj++) {
                sc[nj][0] = ex2_(sc[nj][0] - mn0);
                sc[nj][1] = ex2_(sc[nj][1] - mn0);
                sc[nj][2] = ex2_(sc[nj][2] - mn1);
                sc[nj][3] = ex2_(sc[nj][3] - mn1);
                s0 += sc[nj][0] + sc[nj][1];
                s1 += sc[nj][2] + sc[nj][3];
            }
        }
        s0 += __shfl_xor_sync(0xffffffffu, s0, 1);
        s0 += __shfl_xor_sync(0xffffffffu, s0, 2);
        s1 += __shfl_xor_sync(0xffffffffu, s1, 1);
        s1 += __shfl_xor_sync(0xffffffffu, s1, 2);
        l0s = l0s * al0 + s0;
        l1s = l1s * al1 + s1;

        uint32_t ph[4][4];
#pragma unroll
        for (int ks = 0; ks < 4; ks++) {
            ph[ks][0] = packh2(sc[2 * ks][0],     sc[2 * ks][1]);
            ph[ks][1] = packh2(sc[2 * ks][2],     sc[2 * ks][3]);
            ph[ks][2] = packh2(sc[2 * ks + 1][0], sc[2 * ks + 1][1]);
            ph[ks][3] = packh2(sc[2 * ks + 1][2], sc[2 * ks + 1][3]);
        }

#pragma unroll
        for (int dj = 0; dj < 8; dj += 2) {
#pragma unroll
            for (int u = 0; u < 2; u++) {
                o[dj + u][0] *= al0; o[dj + u][1] *= al0;
                o[dj + u][2] *= al1; o[dj + u][3] *= al1;
            }
#pragma unroll
            for (int ks = 0; ks < 4; ks++) {
                const uint32_t voff = SWZ((uint32_t)(ks * 16 + vRowL) * 128 + dj * 16 + vSeg);
                uint32_t v0, v1, v2, v3;
                ldsm_x4t(v0, v1, v2, v3, stP + 8192 + voff);
                mma_f16(o[dj],     ph[ks], v0, v1);
                mma_f16(o[dj + 1], ph[ks], v2, v3);
            }
        }

        if (doS) {
#pragma unroll
            for (int nj = 0; nj < 8; nj++)
#pragma unroll
                for (int k = 0; k < 4; k++) sc[nj][k] = sn[nj][k];
        }
    }

    const float inv0 = 1.0f / l0s, inv1 = 1.0f / l1s;
#pragma unroll
    for (int dj = 0; dj < 8; dj++) {
        const size_t r0 = ((size_t)b * T_ + row0) * C_ + h * 64 + dj * 8 + q2;
        const size_t r1 = r0 + 8 * C_;
        *(uint32_t*)(y + r0) = packh2(o[dj][0] * inv0, o[dj][1] * inv0);
        *(uint32_t*)(y + r1) = packh2(o[dj][2] * inv1, o[dj][3] * inv1);
    }
}

// ---------------------------------------------------------------------------
extern "C" void kernel_launch(void* const* d_in, const int* in_sizes, int n_in,
                              void* d_out, int out_size)
{
    const float* x      = (const float*)d_in[0];
    const float* w_attn = (const float*)d_in[1];
    const float* b_attn = (const float*)d_in[2];
    const float* w_proj = (const float*)d_in[3];
    const float* b_proj = (const float*)d_in[4];
    float* out = (float*)d_out;

    __half *qkv, *xh, *yh, *wa, *wp;
    cudaGetSymbolAddress((void**)&qkv, g_qkv);
    cudaGetSymbolAddress((void**)&xh, g_x);
    cudaGetSymbolAddress((void**)&yh, g_y);
    cudaGetSymbolAddress((void**)&wa, g_wa);
    cudaGetSymbolAddress((void**)&wp, g_wp);

    cudaFuncSetAttribute(gemm_f16_kernel<0>,
                         cudaFuncAttributeMaxDynamicSharedMemorySize, G_SMEM);
    cudaFuncSetAttribute(gemm_f16_kernel<1>,
                         cudaFuncAttributeMaxDynamicSharedMemorySize, G_SMEM);
    cudaFuncSetAttribute(attn_mma_kernel,
                         cudaFuncAttributeMaxDynamicSharedMemorySize, A_SMEM);

    // conversions
    {
        int n4 = ROWS_ * C_ / 4;
        convert_rows_h_kernel<<<(n4 + 255) / 256, 256>>>(x, xh, n4);
        dim3 bt(32, 8);
        transpose_h_kernel<<<dim3(QKVC_ / 32, C_ / 32), bt>>>(w_attn, wa, C_, QKVC_);
        transpose_h_kernel<<<dim3(C_ / 32,    C_ / 32), bt>>>(w_proj, wp, C_, C_);
    }
    // Stage 1: qkv GEMM (128x128, 2 CTA/SM)
    {
        dim3 grid(QKVC_ / 128, ROWS_ / 128);
        gemm_f16_kernel<1><<<grid, 256, G_SMEM>>>(xh, wa, b_attn, nullptr, qkv,
                                                  ROWS_, QKVC_, C_);
    }
    // Stage 2: attention (64-row CTAs, 2/SM) -> y fp16
    {
        dim3 grid(T_ / 64, B_ * H_);
        attn_mma_kernel<<<grid, 128, A_SMEM>>>(qkv, yh);
    }
    // Stage 3: out = y @ w_proj + b_proj (128x128, 2 CTA/SM)
    {
        dim3 grid(C_ / 128, ROWS_ / 128);
        gemm_f16_kernel<0><<<grid, 256, G_SMEM>>>(yh, wp, b_proj, out, nullptr,
                                                  ROWS_, C_, C_);
    }
}

// round 17
// speedup vs baseline: 1.5059x; 1.5059x over previous
#include <cuda_runtime.h>
#include <cuda_bf16.h>
#include <cuda_fp16.h>
#include <cstdint>

// ---------------------------------------------------------------------------
// CausalSelfAttention on GB300 (sm_103 family target — no 'a' features).
// fp16 1-pass mma.sync scheme (R15 config + attention 3 CTAs/SM):
//   gemm1 (qkv):  128x256 tile, 1 CTA/SM (natural regs, no spills)
//   attention:    64 q-rows/CTA, 128 thr, __launch_bounds__(128,3)
//   gemm3 (proj): 128x128 tile, 1 CTA/SM
// ---------------------------------------------------------------------------

#define B_ 4
#define T_ 2048
#define C_ 768
#define H_ 12
#define ROWS_ 8192
#define QKVC_ 2304

// ---------------- scratch ---------------------------------------------------
__device__ __align__(256) __half  g_qkv[ROWS_ * QKVC_];     // Q(scaled),K,V fp16
__device__ __align__(256) __half  g_x[ROWS_ * C_];          // x fp16
__device__ __align__(256) __half  g_y[ROWS_ * C_];          // y fp16
__device__ __align__(256) __half  g_wa[QKVC_ * C_];         // w_attn^T fp16
__device__ __align__(256) __half  g_wp[C_ * C_];            // w_proj^T fp16

// ---------------- helpers ---------------------------------------------------
__device__ __forceinline__ uint32_t smem_u32(const void* p) {
    uint32_t a;
    asm("{ .reg .u64 t; cvta.to.shared.u64 t, %1; cvt.u32.u64 %0, t; }"
        : "=r"(a) : "l"(p));
    return a;
}
#define SWZ(x) ((x) ^ (((x) >> 3) & 0x70))

__device__ __forceinline__ void cpa16(uint32_t dst, const void* src) {
    asm volatile("cp.async.cg.shared.global [%0], [%1], 16;" :: "r"(dst), "l"(src));
}
__device__ __forceinline__ void cpa_commit() { asm volatile("cp.async.commit_group;"); }

__device__ __forceinline__ void ldsm_x4(uint32_t& r0, uint32_t& r1, uint32_t& r2,
                                        uint32_t& r3, uint32_t addr) {
    asm volatile("ldmatrix.sync.aligned.m8n8.x4.shared.b16 {%0,%1,%2,%3}, [%4];"
                 : "=r"(r0), "=r"(r1), "=r"(r2), "=r"(r3) : "r"(addr));
}
__device__ __forceinline__ void ldsm_x4t(uint32_t& r0, uint32_t& r1, uint32_t& r2,
                                         uint32_t& r3, uint32_t addr) {
    asm volatile("ldmatrix.sync.aligned.m8n8.x4.trans.shared.b16 {%0,%1,%2,%3}, [%4];"
                 : "=r"(r0), "=r"(r1), "=r"(r2), "=r"(r3) : "r"(addr));
}
__device__ __forceinline__ void mma_f16(float* c, const uint32_t* a,
                                        uint32_t b0, uint32_t b1) {
    asm volatile("mma.sync.aligned.m16n8k16.row.col.f32.f16.f16.f32 "
                 "{%0,%1,%2,%3}, {%4,%5,%6,%7}, {%8,%9}, {%0,%1,%2,%3};"
                 : "+f"(c[0]), "+f"(c[1]), "+f"(c[2]), "+f"(c[3])
                 : "r"(a[0]), "r"(a[1]), "r"(a[2]), "r"(a[3]), "r"(b0), "r"(b1));
}
__device__ __forceinline__ float ex2_(float x) {
    float r; asm("ex2.approx.f32 %0, %1;" : "=f"(r) : "f"(x)); return r;
}
__device__ __forceinline__ uint32_t packh2(float a, float b) {
    __half2 hh = __floats2half2_rn(a, b);
    return *(uint32_t*)&hh;
}

// ---------------------------------------------------------------------------
// Conversion kernels
// ---------------------------------------------------------------------------
__global__ void convert_rows_h_kernel(const float* __restrict__ in,
                                      __half* __restrict__ outh, int n4)
{
    int i = blockIdx.x * blockDim.x + threadIdx.x;
    if (i >= n4) return;
    float4 v = ((const float4*)in)[i];
    uint32_t* hp = (uint32_t*)(outh + 4 * (size_t)i);
    hp[0] = packh2(v.x, v.y);
    hp[1] = packh2(v.z, v.w);
}

__global__ void transpose_h_kernel(const float* __restrict__ w,
                                   __half* __restrict__ wT, int K, int N)
{
    __shared__ float t[32][33];
    const int n0 = blockIdx.x * 32, k0 = blockIdx.y * 32;
    const int tx = threadIdx.x, ty = threadIdx.y;
#pragma unroll
    for (int j = 0; j < 4; j++)
        t[ty + j * 8][tx] = w[(size_t)(k0 + ty + j * 8) * N + n0 + tx];
    __syncthreads();
#pragma unroll
    for (int j = 0; j < 4; j++) {
        const int n = ty + j * 8;
        wT[(size_t)(n0 + n) * K + k0 + tx] = __float2half(t[tx][n]);
    }
}

// ---------------------------------------------------------------------------
// GEMM 1 (qkv): 128x256 CTA tile, 8 warps 64x64, fp16 1-pass, 1 CTA/SM.
// Epilogue: fp16 single out; Q columns pre-scaled by log2e/8.
// ---------------------------------------------------------------------------
#define W_STAGE 49152          // A 16K | B 32K
#define W_SMEM  (3 * W_STAGE)

__device__ __forceinline__ void qkv_load_chunk(
    uint32_t sb, const __half* Am, const __half* Bm,
    int rowBase, int colBase, int K, int kc, int stage, int tid)
{
    const uint32_t base = sb + stage * W_STAGE;
    const int k0 = kc * 64;
#pragma unroll
    for (int i = 0; i < 4; i++) {
        const int seg = tid + i * 256;
        const int r = seg >> 3, g = seg & 7;
        cpa16(base + SWZ(r * 128 + g * 16),
              Am + (size_t)(rowBase + r) * K + k0 + g * 8);
    }
#pragma unroll
    for (int i = 0; i < 8; i++) {
        const int seg = tid + i * 256;
        const int r = seg >> 3, g = seg & 7;
        cpa16(base + 16384 + SWZ(r * 128 + g * 16),
              Bm + (size_t)(colBase + r) * K + k0 + g * 8);
    }
    cpa_commit();
}

__global__ __launch_bounds__(256, 1)
void gemm_qkv_kernel(const __half* __restrict__ Am, const __half* __restrict__ Bm,
                     const float* __restrict__ bias, __half* __restrict__ Cq,
                     int M, int N, int K)
{
    extern __shared__ char smem[];
    const uint32_t sb = smem_u32(smem);
    const int tid = threadIdx.x, wid = tid >> 5, lane = tid & 31;
    const int wm = wid >> 2, wn = wid & 3;
    const int rowBase = blockIdx.y * 128, colBase = blockIdx.x * 256;
    const int NK = K / 64;

    float c[4][8][4];
#pragma unroll
    for (int i = 0; i < 4; i++)
#pragma unroll
        for (int j = 0; j < 8; j++)
#pragma unroll
            for (int k = 0; k < 4; k++) c[i][j][k] = 0.f;

    qkv_load_chunk(sb, Am, Bm, rowBase, colBase, K, 0, 0, tid);
    qkv_load_chunk(sb, Am, Bm, rowBase, colBase, K, 1, 1, tid);

    const int aRow = wm * 64 + (lane & 15);
    const uint32_t aSegOff = ((lane >> 4) & 1) * 16;
    const int bRow4 = wn * 64 + ((lane >> 4) & 1) * 8 + (lane & 7);
    const uint32_t bSegOff = ((lane >> 3) & 1) * 16;

    for (int kc = 0; kc < NK; kc++) {
        if (kc + 1 < NK) asm volatile("cp.async.wait_group 1;" ::: "memory");
        else             asm volatile("cp.async.wait_group 0;" ::: "memory");
        __syncthreads();
        if (kc + 2 < NK)
            qkv_load_chunk(sb, Am, Bm, rowBase, colBase, K,
                           kc + 2, (kc + 2) % 3, tid);
        const uint32_t st = sb + (kc % 3) * W_STAGE;
#pragma unroll
        for (int ks = 0; ks < 4; ks++) {
            uint32_t bf[8][2];
#pragma unroll
            for (int nj = 0; nj < 8; nj += 2) {
                const uint32_t boff = SWZ((uint32_t)(bRow4 + nj * 8) * 128 + ks * 32 + bSegOff);
                ldsm_x4(bf[nj][0], bf[nj][1], bf[nj + 1][0], bf[nj + 1][1], st + 16384 + boff);
            }
#pragma unroll
            for (int mi = 0; mi < 4; mi++) {
                uint32_t af[4];
                const uint32_t aoff = SWZ((uint32_t)(aRow + mi * 16) * 128 + ks * 32 + aSegOff);
                ldsm_x4(af[0], af[1], af[2], af[3], st + aoff);
#pragma unroll
                for (int nj = 0; nj < 8; nj++)
                    mma_f16(c[mi][nj], af, bf[nj][0], bf[nj][1]);
            }
        }
    }

    const int g = lane >> 2, q2 = (lane & 3) * 2;
    const int sec = colBase / 768;
    const float scl = (sec == 0) ? 0.18033688f : 1.0f;
#pragma unroll
    for (int mi = 0; mi < 4; mi++) {
        const int row0 = rowBase + wm * 64 + mi * 16 + g;
#pragma unroll
        for (int nj = 0; nj < 8; nj++) {
            const int col = colBase + wn * 64 + nj * 8 + q2;
            const float bx = bias[col], by = bias[col + 1];
            *(uint32_t*)(Cq + (size_t)row0 * N + col) =
                packh2((c[mi][nj][0] + bx) * scl, (c[mi][nj][1] + by) * scl);
            *(uint32_t*)(Cq + (size_t)(row0 + 8) * N + col) =
                packh2((c[mi][nj][2] + bx) * scl, (c[mi][nj][3] + by) * scl);
        }
    }
}

// ---------------------------------------------------------------------------
// GEMM 3 (proj): 128x128 tile, fp16 1-pass, fp32 out, 1 CTA/SM.
// ---------------------------------------------------------------------------
#define P_STAGE 32768          // A 16K | B 16K
#define P_SMEM  (3 * P_STAGE)

__device__ __forceinline__ void proj_load_chunk(
    uint32_t sb, const __half* Am, const __half* Bm,
    int rowBase, int colBase, int K, int kc, int stage, int tid)
{
    const uint32_t base = sb + stage * P_STAGE;
    const int k0 = kc * 64;
#pragma unroll
    for (int i = 0; i < 4; i++) {
        const int seg = tid + i * 256;
        const int r = seg >> 3, g = seg & 7;
        const uint32_t soff = SWZ(r * 128 + g * 16);
        cpa16(base + soff,         Am + (size_t)(rowBase + r) * K + k0 + g * 8);
        cpa16(base + 16384 + soff, Bm + (size_t)(colBase + r) * K + k0 + g * 8);
    }
    cpa_commit();
}

__global__ __launch_bounds__(256, 1)
void gemm_proj_kernel(const __half* __restrict__ Am, const __half* __restrict__ Bm,
                      const float* __restrict__ bias, float* __restrict__ Cm,
                      int M, int N, int K)
{
    extern __shared__ char smem[];
    const uint32_t sb = smem_u32(smem);
    const int tid = threadIdx.x, wid = tid >> 5, lane = tid & 31;
    const int wm = wid >> 2, wn = wid & 3;
    const int rowBase = blockIdx.y * 128, colBase = blockIdx.x * 128;
    const int NK = K / 64;

    float c[4][4][4];
#pragma unroll
    for (int i = 0; i < 4; i++)
#pragma unroll
        for (int j = 0; j < 4; j++)
#pragma unroll
            for (int k = 0; k < 4; k++) c[i][j][k] = 0.f;

    proj_load_chunk(sb, Am, Bm, rowBase, colBase, K, 0, 0, tid);
    proj_load_chunk(sb, Am, Bm, rowBase, colBase, K, 1, 1, tid);

    const int aRow = wm * 64 + (lane & 15);
    const uint32_t aSegOff = ((lane >> 4) & 1) * 16;
    const int bRow4 = wn * 32 + ((lane >> 4) & 1) * 8 + (lane & 7);
    const uint32_t bSegOff = ((lane >> 3) & 1) * 16;

    for (int kc = 0; kc < NK; kc++) {
        if (kc + 1 < NK) asm volatile("cp.async.wait_group 1;" ::: "memory");
        else             asm volatile("cp.async.wait_group 0;" ::: "memory");
        __syncthreads();
        if (kc + 2 < NK)
            proj_load_chunk(sb, Am, Bm, rowBase, colBase, K,
                            kc + 2, (kc + 2) % 3, tid);
        const uint32_t st = sb + (kc % 3) * P_STAGE;
#pragma unroll
        for (int ks = 0; ks < 4; ks++) {
            uint32_t bf[4][2];
#pragma unroll
            for (int nj = 0; nj < 4; nj += 2) {
                const uint32_t boff = SWZ((uint32_t)(bRow4 + nj * 8) * 128 + ks * 32 + bSegOff);
                ldsm_x4(bf[nj][0], bf[nj][1], bf[nj + 1][0], bf[nj + 1][1], st + 16384 + boff);
            }
#pragma unroll
            for (int mi = 0; mi < 4; mi++) {
                uint32_t af[4];
                const uint32_t aoff = SWZ((uint32_t)(aRow + mi * 16) * 128 + ks * 32 + aSegOff);
                ldsm_x4(af[0], af[1], af[2], af[3], st + aoff);
#pragma unroll
                for (int nj = 0; nj < 4; nj++)
                    mma_f16(c[mi][nj], af, bf[nj][0], bf[nj][1]);
            }
        }
    }

    const int g = lane >> 2, q2 = (lane & 3) * 2;
#pragma unroll
    for (int mi = 0; mi < 4; mi++) {
        const int row0 = rowBase + wm * 64 + mi * 16 + g;
#pragma unroll
        for (int nj = 0; nj < 4; nj++) {
            const int col = colBase + wn * 32 + nj * 8 + q2;
            const float bx = bias[col], by = bias[col + 1];
            float2 v0 = make_float2(c[mi][nj][0] + bx, c[mi][nj][1] + by);
            float2 v1 = make_float2(c[mi][nj][2] + bx, c[mi][nj][3] + by);
            *(float2*)(Cm + (size_t)row0 * N + col) = v0;
            *(float2*)(Cm + (size_t)(row0 + 8) * N + col) = v1;
        }
    }
}

// ---------------------------------------------------------------------------
// Flash attention: 64 q-rows/CTA, 128 threads (4 warps x 16 rows),
// __launch_bounds__(128, 3) -> 3 CTAs/SM (reg cap 170, smem 3x56K=168K).
// S fp16 1-pass, PV fp16 1-pass. Single-sync 3-stage ring, stage 16K.
// S(kt+1) interleaved with softmax(kt).
// ---------------------------------------------------------------------------
#define SM_Q  0
#define SM_ST 8192
#define A_STAGE 16384
#define A_SMEM (SM_ST + 3 * A_STAGE)

__device__ __forceinline__ void attn_load_kv(
    uint32_t sb, const __half* qkv, size_t base0, int kBase, int stage, int tid)
{
    const uint32_t st = sb + SM_ST + stage * A_STAGE;
#pragma unroll
    for (int i = 0; i < 4; i++) {
        const int seg = tid + i * 128;
        const int r = seg >> 3, gsg = seg & 7;
        const size_t goff = base0 + (size_t)(kBase + r) * QKVC_ + gsg * 8;
        const uint32_t soff = SWZ((uint32_t)r * 128 + gsg * 16);
        cpa16(st + soff,        qkv + goff + 768);    // K
        cpa16(st + 8192 + soff, qkv + goff + 1536);   // V
    }
    cpa_commit();
}

__global__ __launch_bounds__(128, 3)
void attn_mma_kernel(const __half* __restrict__ qkv, __half* __restrict__ y)
{
    extern __shared__ char smem[];
    const uint32_t sb = smem_u32(smem);
    const int qt = (int)gridDim.x - 1 - (int)blockIdx.x;   // longest first
    const int bh = blockIdx.y;
    const int b = bh / H_, h = bh % H_;
    const int tid = threadIdx.x, wid = tid >> 5, lane = tid & 31;
    const int qBase = qt * 64;
    const size_t base0 = (size_t)b * T_ * QKVC_ + h * 64;
    const int ktMax = qt;

#pragma unroll
    for (int i = 0; i < 4; i++) {
        const int seg = tid + i * 128;
        const int r = seg >> 3, gsg = seg & 7;
        const size_t goff = base0 + (size_t)(qBase + r) * QKVC_ + gsg * 8;
        cpa16(sb + SM_Q + SWZ((uint32_t)r * 128 + gsg * 16), qkv + goff);
    }
    cpa_commit();
    attn_load_kv(sb, qkv, base0, 0, 0, tid);
    attn_load_kv(sb, qkv, base0, (ktMax >= 1) ? 64 : 0, 1, tid);
    asm volatile("cp.async.wait_group 1;" ::: "memory");
    __syncthreads();

    uint32_t qf[4][4];
    {
        const int aRow = wid * 16 + (lane & 15);
        const uint32_t aSeg = ((lane >> 4) & 1) * 16;
#pragma unroll
        for (int ks = 0; ks < 4; ks++) {
            const uint32_t aoff = SWZ((uint32_t)aRow * 128 + ks * 32 + aSeg);
            ldsm_x4(qf[ks][0], qf[ks][1], qf[ks][2], qf[ks][3], sb + SM_Q + aoff);
        }
    }

    float o[8][4];
#pragma unroll
    for (int d = 0; d < 8; d++)
#pragma unroll
        for (int k = 0; k < 4; k++) o[d][k] = 0.f;
    float m0 = -1e30f, m1 = -1e30f, l0s = 0.f, l1s = 0.f;

    const int g = lane >> 2, q2 = (lane & 3) * 2;
    const int qRowMin = qBase + wid * 16;
    const int row0 = qRowMin + g;

    const int bRow4 = ((lane >> 4) & 1) * 8 + (lane & 7);
    const uint32_t bSeg = ((lane >> 3) & 1) * 16;
    const int vRowL = lane & 15;
    const uint32_t vSeg = ((lane >> 4) & 1) * 16;

    float sc[8][4];
    {
        const uint32_t st0 = sb + SM_ST;
#pragma unroll
        for (int nj = 0; nj < 8; nj += 2) {
#pragma unroll
            for (int k = 0; k < 4; k++) { sc[nj][k] = 0.f; sc[nj + 1][k] = 0.f; }
#pragma unroll
            for (int ks = 0; ks < 4; ks++) {
                const uint32_t boff = SWZ((uint32_t)(nj * 8 + bRow4) * 128 + ks * 32 + bSeg);
                uint32_t k0, k1, k2, k3;
                ldsm_x4(k0, k1, k2, k3, st0 + boff);
                mma_f16(sc[nj],     qf[ks], k0, k1);
                mma_f16(sc[nj + 1], qf[ks], k2, k3);
            }
        }
    }

    for (int kt = 0; kt <= ktMax; kt++) {
        const int kBase = kt * 64;
        asm volatile("cp.async.wait_group 0;" ::: "memory");
        __syncthreads();
        if (kt + 2 <= ktMax)
            attn_load_kv(sb, qkv, base0, (kt + 2) * 64, (kt + 2) % 3, tid);

        const bool doS = (kt + 1 <= ktMax);
        const uint32_t stP = sb + SM_ST + (kt % 3) * A_STAGE;
        const uint32_t stS = sb + SM_ST + ((kt + 1) % 3) * A_STAGE;

        if (kt == ktMax) {
#pragma unroll
            for (int nj = 0; nj < 8; nj++) {
                const int col = kBase + nj * 8 + q2;
                if (col > row0)         sc[nj][0] = -1e30f;
                if (col + 1 > row0)     sc[nj][1] = -1e30f;
                if (col > row0 + 8)     sc[nj][2] = -1e30f;
                if (col + 1 > row0 + 8) sc[nj][3] = -1e30f;
            }
        }

        float mx0 = -1e30f, mx1 = -1e30f;
#pragma unroll
        for (int nj = 0; nj < 8; nj++) {
            mx0 = fmaxf(mx0, fmaxf(sc[nj][0], sc[nj][1]));
            mx1 = fmaxf(mx1, fmaxf(sc[nj][2], sc[nj][3]));
        }
        mx0 = fmaxf(mx0, __shfl_xor_sync(0xffffffffu, mx0, 1));
        mx0 = fmaxf(mx0, __shfl_xor_sync(0xffffffffu, mx0, 2));
        mx1 = fmaxf(mx1, __shfl_xor_sync(0xffffffffu, mx1, 1));
        mx1 = fmaxf(mx1, __shfl_xor_sync(0xffffffffu, mx1, 2));
        const float mn0 = fmaxf(m0, mx0), mn1 = fmaxf(m1, mx1);
        const float al0 = ex2_(m0 - mn0), al1 = ex2_(m1 - mn1);
        m0 = mn0; m1 = mn1;

        float s0 = 0.f, s1 = 0.f;
        float sn[8][4];
        if (doS) {
#pragma unroll
            for (int nj = 0; nj < 8; nj += 2) {
#pragma unroll
                for (int k = 0; k < 4; k++) { sn[nj][k] = 0.f; sn[nj + 1][k] = 0.f; }
#pragma unroll
                for (int ks = 0; ks < 4; ks++) {
                    const uint32_t boff = SWZ((uint32_t)(nj * 8 + bRow4) * 128 + ks * 32 + bSeg);
                    uint32_t k0, k1, k2, k3;
                    ldsm_x4(k0, k1, k2, k3, stS + boff);
                    mma_f16(sn[nj],     qf[ks], k0, k1);
                    mma_f16(sn[nj + 1], qf[ks], k2, k3);
                }
#pragma unroll
                for (int u = 0; u < 2; u++) {
                    sc[nj + u][0] = ex2_(sc[nj + u][0] - mn0);
                    sc[nj + u][1] = ex2_(sc[nj + u][1] - mn0);
                    sc[nj + u][2] = ex2_(sc[nj + u][2] - mn1);
                    sc[nj + u][3] = ex2_(sc[nj + u][3] - mn1);
                    s0 += sc[nj + u][0] + sc[nj + u][1];
                    s1 += sc[nj + u][2] + sc[nj + u][3];
                }
            }
        } else {
#pragma unroll
            for (int nj = 0; nj < 8; nj++) {
                sc[nj][0] = ex2_(sc[nj][0] - mn0);
                sc[nj][1] = ex2_(sc[nj][1] - mn0);
                sc[nj][2] = ex2_(sc[nj][2] - mn1);
                sc[nj][3] = ex2_(sc[nj][3] - mn1);
                s0 += sc[nj][0] + sc[nj][1];
                s1 += sc[nj][2] + sc[nj][3];
            }
        }
        s0 += __shfl_xor_sync(0xffffffffu, s0, 1);
        s0 += __shfl_xor_sync(0xffffffffu, s0, 2);
        s1 += __shfl_xor_sync(0xffffffffu, s1, 1);
        s1 += __shfl_xor_sync(0xffffffffu, s1, 2);
        l0s = l0s * al0 + s0;
        l1s = l1s * al1 + s1;

        uint32_t ph[4][4];
#pragma unroll
        for (int ks = 0; ks < 4; ks++) {
            ph[ks][0] = packh2(sc[2 * ks][0],     sc[2 * ks][1]);
            ph[ks][1] = packh2(sc[2 * ks][2],     sc[2 * ks][3]);
            ph[ks][2] = packh2(sc[2 * ks + 1][0], sc[2 * ks + 1][1]);
            ph[ks][3] = packh2(sc[2 * ks + 1][2], sc[2 * ks + 1][3]);
        }

#pragma unroll
        for (int dj = 0; dj < 8; dj += 2) {
#pragma unroll
            for (int u = 0; u < 2; u++) {
                o[dj + u][0] *= al0; o[dj + u][1] *= al0;
                o[dj + u][2] *= al1; o[dj + u][3] *= al1;
            }
#pragma unroll
            for (int ks = 0; ks < 4; ks++) {
                const uint32_t voff = SWZ((uint32_t)(ks * 16 + vRowL) * 128 + dj * 16 + vSeg);
                uint32_t v0, v1, v2, v3;
                ldsm_x4t(v0, v1, v2, v3, stP + 8192 + voff);
                mma_f16(o[dj],     ph[ks], v0, v1);
                mma_f16(o[dj + 1], ph[ks], v2, v3);
            }
        }

        if (doS) {
#pragma unroll
            for (int nj = 0; nj < 8; nj++)
#pragma unroll
                for (int k = 0; k < 4; k++) sc[nj][k] = sn[nj][k];
        }
    }

    const float inv0 = 1.0f / l0s, inv1 = 1.0f / l1s;
#pragma unroll
    for (int dj = 0; dj < 8; dj++) {
        const size_t r0 = ((size_t)b * T_ + row0) * C_ + h * 64 + dj * 8 + q2;
        const size_t r1 = r0 + 8 * C_;
        *(uint32_t*)(y + r0) = packh2(o[dj][0] * inv0, o[dj][1] * inv0);
        *(uint32_t*)(y + r1) = packh2(o[dj][2] * inv1, o[dj][3] * inv1);
    }
}

// ---------------------------------------------------------------------------
extern "C" void kernel_launch(void* const* d_in, const int* in_sizes, int n_in,
                              void* d_out, int out_size)
{
    const float* x      = (const float*)d_in[0];
    const float* w_attn = (const float*)d_in[1];
    const float* b_attn = (const float*)d_in[2];
    const float* w_proj = (const float*)d_in[3];
    const float* b_proj = (const float*)d_in[4];
    float* out = (float*)d_out;

    __half *qkv, *xh, *yh, *wa, *wp;
    cudaGetSymbolAddress((void**)&qkv, g_qkv);
    cudaGetSymbolAddress((void**)&xh, g_x);
    cudaGetSymbolAddress((void**)&yh, g_y);
    cudaGetSymbolAddress((void**)&wa, g_wa);
    cudaGetSymbolAddress((void**)&wp, g_wp);

    cudaFuncSetAttribute(gemm_qkv_kernel,
                         cudaFuncAttributeMaxDynamicSharedMemorySize, W_SMEM);
    cudaFuncSetAttribute(gemm_proj_kernel,
                         cudaFuncAttributeMaxDynamicSharedMemorySize, P_SMEM);
    cudaFuncSetAttribute(attn_mma_kernel,
                         cudaFuncAttributeMaxDynamicSharedMemorySize, A_SMEM);

    // conversions
    {
        int n4 = ROWS_ * C_ / 4;
        convert_rows_h_kernel<<<(n4 + 255) / 256, 256>>>(x, xh, n4);
        dim3 bt(32, 8);
        transpose_h_kernel<<<dim3(QKVC_ / 32, C_ / 32), bt>>>(w_attn, wa, C_, QKVC_);
        transpose_h_kernel<<<dim3(C_ / 32,    C_ / 32), bt>>>(w_proj, wp, C_, C_);
    }
    // Stage 1: qkv GEMM (128x256, 1 CTA/SM)
    {
        dim3 grid(QKVC_ / 256, ROWS_ / 128);
        gemm_qkv_kernel<<<grid, 256, W_SMEM>>>(xh, wa, b_attn, qkv,
                                               ROWS_, QKVC_, C_);
    }
    // Stage 2: attention (64-row CTAs, 3/SM) -> y fp16
    {
        dim3 grid(T_ / 64, B_ * H_);
        attn_mma_kernel<<<grid, 128, A_SMEM>>>(qkv, yh);
    }
    // Stage 3: out = y @ w_proj + b_proj (128x128, 1 CTA/SM)
    {
        dim3 grid(C_ / 128, ROWS_ / 128);
        gemm_proj_kernel<<<grid, 256, P_SMEM>>>(yh, wp, b_proj, out,
                                                ROWS_, C_, C_);
    }
}